// round 7
// baseline (speedup 1.0000x reference)
#include <cuda_runtime.h>

// ---------------------------------------------------------------------------
// Quanvolution2D — closed-form Pauli-algebra evaluation (derivation in R3).
//
//   <Z_i> = sum_T sign * prod_{q in T} sin(w1_q) * prod_{q in A_i\T} cos(w1_q)
//                 * prod_{j in M_T} sin(theta_j) * prod_{j in R_i\M_T} cos(theta_j)
//
// theta = x + w0; masks derived constexpr from the CNOT-ring GF(2) permutation;
// 16 surviving monomials across the 4 filters (compile-time verified).
//
// R7: best-measured shape (91 blocks x 96 threads; 3 warps/CTA = 0.75
// warps/SMSP, 10 patches/warp in channel-in-lane layout) + R6 trims
// (vectorized qw loads issued first, 1/3 folded into compile-time signs).
// Channel sum via explicit-index shuffles so all 3 lanes of a patch hold the
// result and the 4 filter stores spread 2/1/1 across lanes. No smem, no
// barriers, no atomics: bit-deterministic.
// ---------------------------------------------------------------------------

namespace {

constexpr int NQ = 9;

// Forward basis permutation of one CNOT ring: CNOT(0,1), ..., CNOT(8,0)
__host__ __device__ constexpr int permP(int n) {
    int b[NQ] = {};
    for (int i = 0; i < NQ; ++i) b[i] = (n >> i) & 1;
    for (int i = 0; i < NQ; ++i) b[(i + 1) % NQ] ^= b[i];
    int r = 0;
    for (int i = 0; i < NQ; ++i) r |= b[i] << i;
    return r;
}
__host__ __device__ constexpr int invP(int y) {
    for (int n = 0; n < 512; ++n)
        if (permP(n) == y) return n;
    return 0;
}
// bit i of P(P(n)) == parity(n & rowPP(i))
__host__ __device__ constexpr int rowPP(int i) {
    int r = 0;
    for (int j = 0; j < NQ; ++j) {
        int y = permP(permP(1 << j));
        r |= ((y >> i) & 1) << j;
    }
    return r;
}
__host__ __device__ constexpr int cpop(int x) {
    int c = 0;
    while (x) { x &= x - 1; ++c; }
    return c;
}

constexpr int MAXT = 16;

struct TermTab {
    int   rmask[4];         // R_i: theta-support of filter i
    int   amask[4];         // A_i: w1 qubits entering filter i
    int   nt[4];            // surviving term count
    int   smask[4][MAXT];   // M_T: theta-sin mask (subset of R_i)
    int   tsub[4][MAXT];    // T:   w1-sin subset (subset of A_i)
    float sign[4][MAXT];    // +/- 1/3 (channel mean folded in)
    bool  ok;
};

__host__ __device__ constexpr TermTab buildTerms() {
    TermTab T{};
    T.ok = true;
    int M[NQ] = {};
    for (int q = 0; q < NQ; ++q) M[q] = invP(1 << q);
    for (int i = 0; i < 4; ++i) {
        const int R = rowPP(i);
        T.rmask[i] = R;
        int A = 0;
        for (int q = 0; q < NQ; ++q)
            if (cpop(M[q] & R) & 1) A |= 1 << q;
        T.amask[i] = A;
        int n = 0;
        for (int s = 0; s < (1 << NQ); ++s) {
            if (s & ~A) continue;
            int xm = 0;
            for (int q = 0; q < NQ; ++q)
                if ((s >> q) & 1) xm ^= M[q];
            if (xm & ~R) continue;          // any X outside R -> <X>=0, dies
            const int e = cpop(s) + cpop(xm);
            if (e & 1) T.ok = false;        // surviving phase must be real
            if (n >= MAXT) { T.ok = false; continue; }
            T.smask[i][n] = xm;
            T.tsub[i][n]  = s;
            // i^e = +/-1; fold the 1/3 channel mean into the coefficient
            T.sign[i][n]  = (((e & 3) == 0) ? 1.f : -1.f) / 3.f;
            ++n;
        }
        T.nt[i] = n;
    }
    return T;
}

static_assert(buildTerms().ok, "Pauli term table invariant violated");
static_assert(buildTerms().nt[0] >= 1 && buildTerms().nt[1] >= 1 &&
              buildTerms().nt[2] >= 1 && buildTerms().nt[3] >= 1,
              "each filter must have at least the identity term");

constexpr unsigned FULL = 0xffffffffu;

__global__ void __launch_bounds__(96)
quanv_kernel(const float* __restrict__ x, const float* __restrict__ qw,
             float* __restrict__ out) {
    constexpr int C = 3, H = 28, W = 28, HO = 26, WO = 26;
    constexpr int NP = 4 * HO * WO;   // 2704 patches
    constexpr TermTab TT = buildTerms();

    const int lane = threadIdx.x & 31;
    const int wid  = threadIdx.x >> 5;
    const int ch   = lane % 3;            // channel of this lane
    const int pl   = lane / 3;            // patch slot within warp (0..9)
    const int patch = (blockIdx.x * 3 + wid) * 10 + pl;
    const bool act = (lane < 30) && (patch < NP);

    // ---- qw first: w0 gates the theta sincos. 5 vector loads (18 floats). ----
    const float4 qv0 = __ldg((const float4*)(qw + 0));
    const float4 qv1 = __ldg((const float4*)(qw + 4));
    const float4 qv2 = __ldg((const float4*)(qw + 8));
    const float4 qv3 = __ldg((const float4*)(qw + 12));
    const float2 qv4 = __ldg((const float2*)(qw + 16));
    const float w0[NQ] = {qv0.x, qv0.y, qv0.z, qv0.w, qv1.x, qv1.y, qv1.z, qv1.w, qv2.x};
    const float w1[NQ] = {qv2.y, qv2.z, qv2.w, qv3.x, qv3.y, qv3.z, qv3.w, qv4.x, qv4.y};

    const int pc = act ? patch : 0;       // clamp for safe addressing
    const int xo = pc % WO;
    const int yo = (pc / WO) % HO;
    const int b  = pc / (WO * HO);

    // ---- This thread's 9 input loads, front-batched (MLP=9) ----
    const float* xp = x + ((b * C + ch) * H + yo) * W + xo;
    float xv[NQ];
#pragma unroll
    for (int j = 0; j < NQ; ++j)
        xv[j] = __ldg(xp + (j / 3) * W + (j % 3));

    // ---- w1 trig + per-term coefficients (overlaps x-load latency) ----
    float cw[NQ], sw[NQ];
#pragma unroll
    for (int q = 0; q < NQ; ++q)
        __sincosf(w1[q], &sw[q], &cw[q]);

    float coef[4][MAXT];
#pragma unroll
    for (int i = 0; i < 4; ++i) {
#pragma unroll
        for (int t = 0; t < MAXT; ++t) {
            if (t < TT.nt[i]) {
                float p = TT.sign[i][t];
#pragma unroll
                for (int q = 0; q < NQ; ++q) {
                    if ((TT.amask[i] >> q) & 1)
                        p *= ((TT.tsub[i][t] >> q) & 1) ? sw[q] : cw[q];
                }
                coef[i][t] = p;
            }
        }
    }

    // ---- theta trig (9 independent fast sincos) ----
    float cth[NQ], sth[NQ];
#pragma unroll
    for (int j = 0; j < NQ; ++j)
        __sincosf(xv[j] + w0[j], &sth[j], &cth[j]);

    // ---- 16 monomials across 4 filters ----
    float z[4];
#pragma unroll
    for (int i = 0; i < 4; ++i) {
        float zi = 0.f;
#pragma unroll
        for (int t = 0; t < MAXT; ++t) {
            if (t < TT.nt[i]) {
                float p = coef[i][t];
#pragma unroll
                for (int j = 0; j < NQ; ++j) {
                    if ((TT.rmask[i] >> j) & 1)
                        p *= ((TT.smask[i][t] >> j) & 1) ? sth[j] : cth[j];
                }
                zi += p;
            }
        }
        z[i] = zi;
    }

    // ---- Channel sum via explicit-index shuffles: every lane of the triple
    // {3p, 3p+1, 3p+2} obtains the same fixed-order sum (deterministic).
    // The 1/3 factor is already folded into coef.
    const int base = lane - ch;           // = 3*pl
#pragma unroll
    for (int f = 0; f < 4; ++f) {
        float z0 = __shfl_sync(FULL, z[f], base);
        float z1 = __shfl_sync(FULL, z[f], base + 1);
        float z2 = __shfl_sync(FULL, z[f], base + 2);
        z[f] = z0 + z1 + z2;
    }

    // Spread the 4 filter stores across the 3 lanes of each patch (2/1/1).
    if (act) {
        float* op = out + (b * 4 * HO + yo) * WO + xo;
        if (ch == 0) {
            op[0]           = z[0];
            op[HO * WO]     = z[1];
        } else if (ch == 1) {
            op[2 * HO * WO] = z[2];
        } else {
            op[3 * HO * WO] = z[3];
        }
    }
}

}  // namespace

extern "C" void kernel_launch(void* const* d_in, const int* in_sizes, int n_in,
                              void* d_out, int out_size) {
    const float* x  = (const float*)d_in[0];   // (4,3,28,28) float32
    const float* qw = (const float*)d_in[1];   // (2,9) float32
    float* out = (float*)d_out;                // (4,4,26,26) float32

    // 30 patches per 96-thread block (10 per warp): ceil(2704/30) = 91 blocks.
    quanv_kernel<<<91, 96>>>(x, qw, out);
}

// round 8
// speedup vs baseline: 1.1020x; 1.1020x over previous
#include <cuda_runtime.h>

// ---------------------------------------------------------------------------
// Quanvolution2D — closed-form Pauli-algebra evaluation (derivation in R3).
//
//   <Z_i> = sum_T sign * prod_{q in T} sin(w1_q) * prod_{q in A_i\T} cos(w1_q)
//                 * prod_{j in M_T} sin(theta_j) * prod_{j in R_i\M_T} cos(theta_j)
//
// theta = x + w0; masks derived constexpr from the CNOT-ring GF(2) permutation;
// 16 surviving monomials across the 4 filters (compile-time verified).
//
// R8 (final form): the minimum-measured configuration.
//  - 91 blocks x 96 threads; channel-in-lane layout (lane = 3*patch_local+ch)
//  - channel sum: two __shfl_down_sync, fixed order (deterministic), lane ch==0
//    stores all 4 filters
//  - qw loaded first & vectorized (float4/float2); 1/3 folded into constexpr
//    coefficient signs
//  - no smem, no barriers, no atomics
// Remaining span is launch/replay overhead (~5000 cy) — confirmed invariant
// across 3x variation in kernel-internal work (R3-R7).
// ---------------------------------------------------------------------------

namespace {

constexpr int NQ = 9;

// Forward basis permutation of one CNOT ring: CNOT(0,1), ..., CNOT(8,0)
__host__ __device__ constexpr int permP(int n) {
    int b[NQ] = {};
    for (int i = 0; i < NQ; ++i) b[i] = (n >> i) & 1;
    for (int i = 0; i < NQ; ++i) b[(i + 1) % NQ] ^= b[i];
    int r = 0;
    for (int i = 0; i < NQ; ++i) r |= b[i] << i;
    return r;
}
__host__ __device__ constexpr int invP(int y) {
    for (int n = 0; n < 512; ++n)
        if (permP(n) == y) return n;
    return 0;
}
// bit i of P(P(n)) == parity(n & rowPP(i))
__host__ __device__ constexpr int rowPP(int i) {
    int r = 0;
    for (int j = 0; j < NQ; ++j) {
        int y = permP(permP(1 << j));
        r |= ((y >> i) & 1) << j;
    }
    return r;
}
__host__ __device__ constexpr int cpop(int x) {
    int c = 0;
    while (x) { x &= x - 1; ++c; }
    return c;
}

constexpr int MAXT = 16;

struct TermTab {
    int   rmask[4];         // R_i: theta-support of filter i
    int   amask[4];         // A_i: w1 qubits entering filter i
    int   nt[4];            // surviving term count
    int   smask[4][MAXT];   // M_T: theta-sin mask (subset of R_i)
    int   tsub[4][MAXT];    // T:   w1-sin subset (subset of A_i)
    float sign[4][MAXT];    // +/- 1/3 (channel mean folded in)
    bool  ok;
};

__host__ __device__ constexpr TermTab buildTerms() {
    TermTab T{};
    T.ok = true;
    int M[NQ] = {};
    for (int q = 0; q < NQ; ++q) M[q] = invP(1 << q);
    for (int i = 0; i < 4; ++i) {
        const int R = rowPP(i);
        T.rmask[i] = R;
        int A = 0;
        for (int q = 0; q < NQ; ++q)
            if (cpop(M[q] & R) & 1) A |= 1 << q;
        T.amask[i] = A;
        int n = 0;
        for (int s = 0; s < (1 << NQ); ++s) {
            if (s & ~A) continue;
            int xm = 0;
            for (int q = 0; q < NQ; ++q)
                if ((s >> q) & 1) xm ^= M[q];
            if (xm & ~R) continue;          // any X outside R -> <X>=0, dies
            const int e = cpop(s) + cpop(xm);
            if (e & 1) T.ok = false;        // surviving phase must be real
            if (n >= MAXT) { T.ok = false; continue; }
            T.smask[i][n] = xm;
            T.tsub[i][n]  = s;
            // i^e = +/-1; fold the 1/3 channel mean into the coefficient
            T.sign[i][n]  = (((e & 3) == 0) ? 1.f : -1.f) / 3.f;
            ++n;
        }
        T.nt[i] = n;
    }
    return T;
}

static_assert(buildTerms().ok, "Pauli term table invariant violated");
static_assert(buildTerms().nt[0] >= 1 && buildTerms().nt[1] >= 1 &&
              buildTerms().nt[2] >= 1 && buildTerms().nt[3] >= 1,
              "each filter must have at least the identity term");

constexpr unsigned FULL = 0xffffffffu;

__global__ void __launch_bounds__(96)
quanv_kernel(const float* __restrict__ x, const float* __restrict__ qw,
             float* __restrict__ out) {
    constexpr int C = 3, H = 28, W = 28, HO = 26, WO = 26;
    constexpr int NP = 4 * HO * WO;   // 2704 patches
    constexpr TermTab TT = buildTerms();

    const int lane = threadIdx.x & 31;
    const int wid  = threadIdx.x >> 5;
    const int ch   = lane % 3;            // channel of this lane
    const int pl   = lane / 3;            // patch slot within warp (0..9)
    const int patch = (blockIdx.x * 3 + wid) * 10 + pl;
    const bool act = (lane < 30) && (patch < NP);

    // ---- qw first: w0 gates the theta sincos. 5 vector loads (18 floats). ----
    const float4 qv0 = __ldg((const float4*)(qw + 0));
    const float4 qv1 = __ldg((const float4*)(qw + 4));
    const float4 qv2 = __ldg((const float4*)(qw + 8));
    const float4 qv3 = __ldg((const float4*)(qw + 12));
    const float2 qv4 = __ldg((const float2*)(qw + 16));
    const float w0[NQ] = {qv0.x, qv0.y, qv0.z, qv0.w, qv1.x, qv1.y, qv1.z, qv1.w, qv2.x};
    const float w1[NQ] = {qv2.y, qv2.z, qv2.w, qv3.x, qv3.y, qv3.z, qv3.w, qv4.x, qv4.y};

    const int pc = act ? patch : 0;       // clamp for safe addressing
    const int xo = pc % WO;
    const int yo = (pc / WO) % HO;
    const int b  = pc / (WO * HO);

    // ---- This thread's 9 input loads, front-batched (MLP=9) ----
    const float* xp = x + ((b * C + ch) * H + yo) * W + xo;
    float xv[NQ];
#pragma unroll
    for (int j = 0; j < NQ; ++j)
        xv[j] = __ldg(xp + (j / 3) * W + (j % 3));

    // ---- w1 trig + per-term coefficients (overlaps x-load latency) ----
    float cw[NQ], sw[NQ];
#pragma unroll
    for (int q = 0; q < NQ; ++q)
        __sincosf(w1[q], &sw[q], &cw[q]);

    float coef[4][MAXT];
#pragma unroll
    for (int i = 0; i < 4; ++i) {
#pragma unroll
        for (int t = 0; t < MAXT; ++t) {
            if (t < TT.nt[i]) {
                float p = TT.sign[i][t];
#pragma unroll
                for (int q = 0; q < NQ; ++q) {
                    if ((TT.amask[i] >> q) & 1)
                        p *= ((TT.tsub[i][t] >> q) & 1) ? sw[q] : cw[q];
                }
                coef[i][t] = p;
            }
        }
    }

    // ---- theta trig (9 independent fast sincos) ----
    float cth[NQ], sth[NQ];
#pragma unroll
    for (int j = 0; j < NQ; ++j)
        __sincosf(xv[j] + w0[j], &sth[j], &cth[j]);

    // ---- 16 monomials across 4 filters ----
    float z[4];
#pragma unroll
    for (int i = 0; i < 4; ++i) {
        float zi = 0.f;
#pragma unroll
        for (int t = 0; t < MAXT; ++t) {
            if (t < TT.nt[i]) {
                float p = coef[i][t];
#pragma unroll
                for (int j = 0; j < NQ; ++j) {
                    if ((TT.rmask[i] >> j) & 1)
                        p *= ((TT.smask[i][t] >> j) & 1) ? sth[j] : cth[j];
                }
                zi += p;
            }
        }
        z[i] = zi;
    }

    // ---- Channel sum: lanes 3p,3p+1,3p+2 hold the 3 channels of patch p.
    // Capture both partners first, then sum in fixed order (deterministic).
    // The 1/3 factor is already folded into coef.
#pragma unroll
    for (int f = 0; f < 4; ++f) {
        float z1 = __shfl_down_sync(FULL, z[f], 1);
        float z2 = __shfl_down_sync(FULL, z[f], 2);
        z[f] = z[f] + z1 + z2;
    }

    if (act && ch == 0) {
        float* op = out + (b * 4 * HO + yo) * WO + xo;
#pragma unroll
        for (int f = 0; f < 4; ++f)
            op[f * HO * WO] = z[f];
    }
}

}  // namespace

extern "C" void kernel_launch(void* const* d_in, const int* in_sizes, int n_in,
                              void* d_out, int out_size) {
    const float* x  = (const float*)d_in[0];   // (4,3,28,28) float32
    const float* qw = (const float*)d_in[1];   // (2,9) float32
    float* out = (float*)d_out;                // (4,4,26,26) float32

    // 30 patches per 96-thread block (10 per warp): ceil(2704/30) = 91 blocks.
    quanv_kernel<<<91, 96>>>(x, qw, out);
}